// round 6
// baseline (speedup 1.0000x reference)
#include <cuda_runtime.h>
#include <cuda_fp16.h>
#include <cstdint>

#define NDIM   32
#define DDIM   256
#define HDIM   1024
#define HC     128
#define NCHUNK 8
#define THREADS 256

// strides in halves; rows ≡ 4 mod 32 words -> conflict-free ldmatrix
#define XH_H 264
#define W1_H 136
#define W2_H 264
#define HS_H 136

// byte offsets
#define SMEM_XH 0          // half [32][264]          = 16896
#define SMEM_W1 16896      // half [256][136]         = 69632
#define SMEM_W2 86528      // half [128][264]         = 67584
#define SMEM_HS 154112     // half [2g][2par][2i][32][136] = 69632
#define HS_BUF  8704       // one 32x136 half buffer
#define SMEM_TOTAL 223744  // < 227KB opt-in

__device__ __forceinline__ unsigned smem_u32(const void* p) {
    unsigned a;
    asm("{ .reg .u64 t; cvta.to.shared.u64 t, %1; cvt.u32.u64 %0, t; }" : "=r"(a) : "l"(p));
    return a;
}
__device__ __forceinline__ void ldsm4(unsigned r[4], unsigned a) {
    asm volatile("ldmatrix.sync.aligned.m8n8.x4.shared.b16 {%0,%1,%2,%3}, [%4];\n"
                 : "=r"(r[0]), "=r"(r[1]), "=r"(r[2]), "=r"(r[3]) : "r"(a));
}
__device__ __forceinline__ void ldsm4t(unsigned r[4], unsigned a) {
    asm volatile("ldmatrix.sync.aligned.m8n8.x4.trans.shared.b16 {%0,%1,%2,%3}, [%4];\n"
                 : "=r"(r[0]), "=r"(r[1]), "=r"(r[2]), "=r"(r[3]) : "r"(a));
}
__device__ __forceinline__ void mma16816(float d[4], const unsigned a[4],
                                         unsigned b0, unsigned b1) {
    asm volatile("mma.sync.aligned.m16n8k16.row.col.f32.f16.f16.f32 "
                 "{%0,%1,%2,%3}, {%4,%5,%6,%7}, {%8,%9}, {%0,%1,%2,%3};\n"
                 : "+f"(d[0]), "+f"(d[1]), "+f"(d[2]), "+f"(d[3])
                 : "r"(a[0]), "r"(a[1]), "r"(a[2]), "r"(a[3]), "r"(b0), "r"(b1));
}
__device__ __forceinline__ unsigned hmul2u(unsigned a, __half2 s) {
    __half2 r = __hmul2(*(__half2*)&a, s);
    return *(unsigned*)&r;
}

__global__ __launch_bounds__(THREADS, 1)
void fused_pair_mlp_v3(const float* __restrict__ X,  const float* __restrict__ W1g,
                       const float* __restrict__ b1g, const float* __restrict__ W2g,
                       const float* __restrict__ b2g, float* __restrict__ out)
{
    extern __shared__ unsigned char smem[];
    __half* Xhp = (__half*)(smem + SMEM_XH);
    __half* W1p = (__half*)(smem + SMEM_W1);
    __half* W2p = (__half*)(smem + SMEM_W2);

    const int b = blockIdx.x, tid = threadIdx.x;
    const int w = tid >> 5, lane = tid & 31;
    const int g = w >> 2;         // two groups of 4 warps
    const int wg = w & 3;
    const int gid = lane >> 2, tig = lane & 3;

    // ---- stage X_b as fp16 [32, 264-stride] once
    {
        const float4* xg = (const float4*)(X + (size_t)b * NDIM * DDIM);
        for (int q = tid; q < 1024; q += THREADS) {
            int row = q >> 5, f = q & 31;            // 8 halves per q
            float4 v0 = xg[row * 64 + f * 2];
            float4 v1 = xg[row * 64 + f * 2 + 1];
            __half2 h0 = __floats2half2_rn(v0.x, v0.y);
            __half2 h1 = __floats2half2_rn(v0.z, v0.w);
            __half2 h2 = __floats2half2_rn(v1.x, v1.y);
            __half2 h3 = __floats2half2_rn(v1.z, v1.w);
            uint4 u = make_uint4(*(unsigned*)&h0, *(unsigned*)&h1,
                                 *(unsigned*)&h2, *(unsigned*)&h3);
            *(uint4*)(Xhp + row * XH_H + f * 8) = u;
        }
    }

    // ldmatrix per-lane address components
    const int mat = lane >> 3, mr = lane & 7;
    const int lrow = (mat & 1) * 8 + mr;
    const int kh   = (mat >> 1) * 8;

    const unsigned aXA  = smem_u32(Xhp) + (unsigned)(lrow * XH_H + kh) * 2u;
    const unsigned aB1  = smem_u32(W1p) + (unsigned)(lrow * W1_H + 32 * wg + kh) * 2u;
    const unsigned aB2  = smem_u32(W2p) + (unsigned)(lrow * W2_H + 64 * wg + kh) * 2u;
    const unsigned aHS0 = smem_u32(smem + SMEM_HS) + (unsigned)(g * 4 * HS_BUF)
                        + (unsigned)(lrow * HS_H + kh) * 2u;

    // persistent out accumulator: warp owns out cols [64wg, 64wg+64)
    float oacc[2][8][4];
    #pragma unroll
    for (int m = 0; m < 2; ++m)
        #pragma unroll
        for (int t = 0; t < 8; ++t)
            #pragma unroll
            for (int r = 0; r < 4; ++r) oacc[m][t][r] = 0.f;

    for (int c = 0; c < NCHUNK; ++c) {
        __syncthreads();  // prev chunk readers done

        // stage W1 chunk [256 x 128] -> half
        for (int q = tid; q < 8192; q += THREADS) {
            int d = q >> 5, f = q & 31;
            float4 v = *(const float4*)(W1g + (size_t)d * HDIM + c * HC + f * 4);
            __half2 h01 = __floats2half2_rn(v.x, v.y);
            __half2 h23 = __floats2half2_rn(v.z, v.w);
            *(uint2*)(W1p + d * W1_H + f * 4) = make_uint2(*(unsigned*)&h01, *(unsigned*)&h23);
        }
        // stage W2 chunk [128 x 256] -> half
        for (int q = tid; q < 8192; q += THREADS) {
            int h = q >> 6, f = q & 63;
            float4 v = *(const float4*)(W2g + (size_t)(c * HC + h) * DDIM + f * 4);
            __half2 h01 = __floats2half2_rn(v.x, v.y);
            __half2 h23 = __floats2half2_rn(v.z, v.w);
            *(uint2*)(W2p + h * W2_H + f * 4) = make_uint2(*(unsigned*)&h01, *(unsigned*)&h23);
        }
        float b1v[4][2];
        #pragma unroll
        for (int t = 0; t < 4; ++t) {
            b1v[t][0] = __ldg(b1g + c * HC + 32 * wg + 8 * t + 2 * tig);
            b1v[t][1] = __ldg(b1g + c * HC + 32 * wg + 8 * t + 2 * tig + 1);
        }
        __syncthreads();  // W chunk ready

        for (int ii = 0; ii < 8; ++ii) {
            const int i0 = 4 * ii + 2 * g;      // group-private pair of i's
            const int i1 = i0 + 1;
            const int par = ii & 1;
            const __half* Xi0 = Xhp + i0 * XH_H;
            const __half* Xi1 = Xhp + i1 * XH_H;

            // ---- GEMM1 (both i's): h[i][32, 32wg..+32] = P_i @ W1, K=256
            float ha0[2][4][4], ha1[2][4][4];
            #pragma unroll
            for (int m = 0; m < 2; ++m)
                #pragma unroll
                for (int t = 0; t < 4; ++t)
                    #pragma unroll
                    for (int r = 0; r < 4; ++r) { ha0[m][t][r] = 0.f; ha1[m][t][r] = 0.f; }

            #pragma unroll 4
            for (int kk = 0; kk < 16; ++kk) {
                unsigned xA0[4], xA1[4];
                ldsm4(xA0, aXA + (unsigned)(kk * 32));
                ldsm4(xA1, aXA + (unsigned)(kk * 32 + 16 * XH_H * 2));
                __half2 x0a = *(const __half2*)(Xi0 + kk * 16 + 2 * tig);
                __half2 x0b = *(const __half2*)(Xi0 + kk * 16 + 2 * tig + 8);
                __half2 x1a = *(const __half2*)(Xi1 + kk * 16 + 2 * tig);
                __half2 x1b = *(const __half2*)(Xi1 + kk * 16 + 2 * tig + 8);
                unsigned A00[4], A01[4], A10[4], A11[4];
                A00[0] = hmul2u(xA0[0], x0a); A00[1] = hmul2u(xA0[1], x0a);
                A00[2] = hmul2u(xA0[2], x0b); A00[3] = hmul2u(xA0[3], x0b);
                A01[0] = hmul2u(xA1[0], x0a); A01[1] = hmul2u(xA1[1], x0a);
                A01[2] = hmul2u(xA1[2], x0b); A01[3] = hmul2u(xA1[3], x0b);
                A10[0] = hmul2u(xA0[0], x1a); A10[1] = hmul2u(xA0[1], x1a);
                A10[2] = hmul2u(xA0[2], x1b); A10[3] = hmul2u(xA0[3], x1b);
                A11[0] = hmul2u(xA1[0], x1a); A11[1] = hmul2u(xA1[1], x1a);
                A11[2] = hmul2u(xA1[2], x1b); A11[3] = hmul2u(xA1[3], x1b);
                unsigned B[8];
                unsigned bk = aB1 + (unsigned)(kk * 16 * W1_H * 2);
                ldsm4t(B, bk);
                ldsm4t(B + 4, bk + 32);
                #pragma unroll
                for (int t = 0; t < 4; ++t) {
                    mma16816(ha0[0][t], A00, B[2 * t], B[2 * t + 1]);
                    mma16816(ha0[1][t], A01, B[2 * t], B[2 * t + 1]);
                    mma16816(ha1[0][t], A10, B[2 * t], B[2 * t + 1]);
                    mma16816(ha1[1][t], A11, B[2 * t], B[2 * t + 1]);
                }
            }

            // ---- bias + relu -> 2 Hs buffers (parity-selected)
            __half* Hb0 = (__half*)(smem + SMEM_HS) + (g * 4 + par * 2)     * (HS_BUF / 2);
            __half* Hb1 = (__half*)(smem + SMEM_HS) + (g * 4 + par * 2 + 1) * (HS_BUF / 2);
            #pragma unroll
            for (int m = 0; m < 2; ++m) {
                #pragma unroll
                for (int t = 0; t < 4; ++t) {
                    int col = 32 * wg + 8 * t + 2 * tig;
                    int r0 = 16 * m + gid;
                    float f0 = fmaxf(ha0[m][t][0] + b1v[t][0], 0.f);
                    float f1 = fmaxf(ha0[m][t][1] + b1v[t][1], 0.f);
                    float f2 = fmaxf(ha0[m][t][2] + b1v[t][0], 0.f);
                    float f3 = fmaxf(ha0[m][t][3] + b1v[t][1], 0.f);
                    *(__half2*)(Hb0 + r0 * HS_H + col)       = __floats2half2_rn(f0, f1);
                    *(__half2*)(Hb0 + (r0 + 8) * HS_H + col) = __floats2half2_rn(f2, f3);
                    float g0 = fmaxf(ha1[m][t][0] + b1v[t][0], 0.f);
                    float g1 = fmaxf(ha1[m][t][1] + b1v[t][1], 0.f);
                    float g2 = fmaxf(ha1[m][t][2] + b1v[t][0], 0.f);
                    float g3 = fmaxf(ha1[m][t][3] + b1v[t][1], 0.f);
                    *(__half2*)(Hb1 + r0 * HS_H + col)       = __floats2half2_rn(g0, g1);
                    *(__half2*)(Hb1 + (r0 + 8) * HS_H + col) = __floats2half2_rn(g2, g3);
                }
            }
            asm volatile("bar.sync %0, %1;" :: "r"(1 + g), "r"(128));  // h tiles ready

            // ---- GEMM2: oacc += h0 @ W2  +  h1 @ W2  (B fragments shared)
            const unsigned aH0 = aHS0 + (unsigned)(par * 2 * HS_BUF);
            const unsigned aH1 = aH0 + (unsigned)HS_BUF;
            #pragma unroll 2
            for (int kk = 0; kk < 8; ++kk) {
                unsigned A00[4], A01[4], A10[4], A11[4], Bb[16];
                ldsm4(A00, aH0 + (unsigned)(kk * 32));
                ldsm4(A01, aH0 + (unsigned)(kk * 32 + 16 * HS_H * 2));
                ldsm4(A10, aH1 + (unsigned)(kk * 32));
                ldsm4(A11, aH1 + (unsigned)(kk * 32 + 16 * HS_H * 2));
                unsigned bk = aB2 + (unsigned)(kk * 16 * W2_H * 2);
                ldsm4t(Bb,      bk);
                ldsm4t(Bb + 4,  bk + 32);
                ldsm4t(Bb + 8,  bk + 64);
                ldsm4t(Bb + 12, bk + 96);
                #pragma unroll
                for (int t = 0; t < 8; ++t) {
                    mma16816(oacc[0][t], A00, Bb[2 * t], Bb[2 * t + 1]);
                    mma16816(oacc[1][t], A01, Bb[2 * t], Bb[2 * t + 1]);
                }
                #pragma unroll
                for (int t = 0; t < 8; ++t) {
                    mma16816(oacc[0][t], A10, Bb[2 * t], Bb[2 * t + 1]);
                    mma16816(oacc[1][t], A11, Bb[2 * t], Bb[2 * t + 1]);
                }
            }
        }
    }

    // ---- epilogue: cross-group reduce via smem (Xh/W1 dead), add 32*b2
    __syncthreads();
    float* Os = (float*)smem;   // 32KB scratch over dead Xh+W1 regions
    if (g == 1) {
        #pragma unroll
        for (int t = 0; t < 8; ++t) {
            int col = 64 * wg + 8 * t + 2 * tig;
            #pragma unroll
            for (int m = 0; m < 2; ++m) {
                int r0 = 16 * m + gid;
                *(float2*)(Os + r0 * DDIM + col)       = make_float2(oacc[m][t][0], oacc[m][t][1]);
                *(float2*)(Os + (r0 + 8) * DDIM + col) = make_float2(oacc[m][t][2], oacc[m][t][3]);
            }
        }
    }
    __syncthreads();
    if (g == 0) {
        float* og = out + (size_t)b * NDIM * DDIM;
        #pragma unroll
        for (int t = 0; t < 8; ++t) {
            int col = 64 * wg + 8 * t + 2 * tig;
            float bb0 = 32.0f * __ldg(b2g + col);
            float bb1 = 32.0f * __ldg(b2g + col + 1);
            #pragma unroll
            for (int m = 0; m < 2; ++m) {
                int r0 = 16 * m + gid;
                float2 s0 = *(float2*)(Os + r0 * DDIM + col);
                float2 s1 = *(float2*)(Os + (r0 + 8) * DDIM + col);
                *(float2*)(og + (size_t)r0 * DDIM + col) =
                    make_float2(oacc[m][t][0] + s0.x + bb0, oacc[m][t][1] + s0.y + bb1);
                *(float2*)(og + (size_t)(r0 + 8) * DDIM + col) =
                    make_float2(oacc[m][t][2] + s1.x + bb0, oacc[m][t][3] + s1.y + bb1);
            }
        }
    }
}

extern "C" void kernel_launch(void* const* d_in, const int* in_sizes, int n_in,
                              void* d_out, int out_size) {
    (void)in_sizes; (void)n_in; (void)out_size;
    const float* X  = (const float*)d_in[0];   // [128,32,256]
    const float* W1 = (const float*)d_in[1];   // [256,1024]
    const float* b1 = (const float*)d_in[2];   // [1024]
    const float* W2 = (const float*)d_in[3];   // [1024,256]
    const float* b2 = (const float*)d_in[4];   // [256]
    float* out = (float*)d_out;                // [128,32,256]

    cudaFuncSetAttribute(fused_pair_mlp_v3,
                         cudaFuncAttributeMaxDynamicSharedMemorySize, SMEM_TOTAL);
    fused_pair_mlp_v3<<<128, THREADS, SMEM_TOTAL>>>(X, W1, b1, W2, b2, out);
}

// round 7
// speedup vs baseline: 1.0537x; 1.0537x over previous
#include <cuda_runtime.h>
#include <cuda_fp16.h>
#include <cstdint>

#define NDIM   32
#define DDIM   256
#define HDIM   1024
#define HC     128
#define NCHUNK 8
#define THREADS 256

// smem layout (bytes) — all tiles XOR-swizzled, no padding
#define SMEM_PS 0           // 4 bufs x 16384  : P [32 j][512B]
#define PS_BUF  16384
#define SMEM_W1 65536       // [256 d][256B]   : W1 chunk (k-major)
#define SMEM_W2 131072      // [128 h][512B]   : W2 chunk (k-major)
#define SMEM_HS 196608      // 4 bufs x 8192   : h [32 j][256B]
#define HS_BUF  8192
#define SMEM_TOTAL 229376   // 224KB

__device__ __forceinline__ unsigned smem_u32(const void* p) {
    unsigned a;
    asm("{ .reg .u64 t; cvta.to.shared.u64 t, %1; cvt.u32.u64 %0, t; }" : "=r"(a) : "l"(p));
    return a;
}
__device__ __forceinline__ void ldsm4(unsigned r[4], unsigned a) {
    asm volatile("ldmatrix.sync.aligned.m8n8.x4.shared.b16 {%0,%1,%2,%3}, [%4];\n"
                 : "=r"(r[0]), "=r"(r[1]), "=r"(r[2]), "=r"(r[3]) : "r"(a));
}
__device__ __forceinline__ void ldsm4t(unsigned r[4], unsigned a) {
    asm volatile("ldmatrix.sync.aligned.m8n8.x4.trans.shared.b16 {%0,%1,%2,%3}, [%4];\n"
                 : "=r"(r[0]), "=r"(r[1]), "=r"(r[2]), "=r"(r[3]) : "r"(a));
}
__device__ __forceinline__ void mma16816(float d[4], const unsigned a[4],
                                         unsigned b0, unsigned b1) {
    asm volatile("mma.sync.aligned.m16n8k16.row.col.f32.f16.f16.f32 "
                 "{%0,%1,%2,%3}, {%4,%5,%6,%7}, {%8,%9}, {%0,%1,%2,%3};\n"
                 : "+f"(d[0]), "+f"(d[1]), "+f"(d[2]), "+f"(d[3])
                 : "r"(a[0]), "r"(a[1]), "r"(a[2]), "r"(a[3]), "r"(b0), "r"(b1));
}
__device__ __forceinline__ unsigned hmul2u(unsigned a, unsigned b) {
    __half2 r = __hmul2(*(__half2*)&a, *(__half2*)&b);
    return *(unsigned*)&r;
}
__device__ __forceinline__ unsigned f2h2u(float x, float y) {
    __half2 h = __floats2half2_rn(x, y);
    return *(unsigned*)&h;
}

__global__ __launch_bounds__(THREADS, 1)
void fused_pair_mlp_v4(const float* __restrict__ X,  const float* __restrict__ W1g,
                       const float* __restrict__ b1g, const float* __restrict__ W2g,
                       const float* __restrict__ b2g, float* __restrict__ out)
{
    extern __shared__ unsigned char smem[];
    const int b = blockIdx.x, tid = threadIdx.x;
    const int w = tid >> 5, lane = tid & 31;
    const int g = w >> 2, wg = w & 3;
    const int gtid = tid & 127;
    const int gid = lane >> 2, tig = lane & 3;

    // ldmatrix lane mapping (R5-identical)
    const int mat  = lane >> 3, mr = lane & 7;
    const int lrow = (mat & 1) * 8 + mr;   // row within 16
    const int kb   = mat >> 1;             // 16B-unit offset (kh/8)
    const int xr   = lrow & 7;             // swizzle XOR key

    const unsigned sb = smem_u32(smem);
    const unsigned uP0 = sb + SMEM_PS + (unsigned)(g * 2) * PS_BUF;
    const unsigned uP1 = uP0 + PS_BUF;
    const unsigned uH0 = sb + SMEM_HS + (unsigned)(g * 2) * HS_BUF;
    const unsigned uH1 = uH0 + HS_BUF;
    unsigned char* Pb0 = smem + SMEM_PS + (g * 2) * PS_BUF;
    unsigned char* Pb1 = Pb0 + PS_BUF;
    unsigned char* Hb0 = smem + SMEM_HS + (g * 2) * HS_BUF;
    unsigned char* Hb1 = Hb0 + HS_BUF;

    // A(P) lane row bases (rows 0-15 / 16-31), 512B rows
    const unsigned pa_r0 = (unsigned)(lrow * 512);
    const unsigned pa_r1 = (unsigned)((lrow + 16) * 512);
    // B1 (W1, 256B rows): two ldsm4t per kk covering n-cols [32wg,32wg+32)
    const unsigned b1a = sb + SMEM_W1 + (unsigned)(lrow * 256) + ((((unsigned)(4 * wg + kb)) ^ xr) << 4);
    const unsigned b1b = sb + SMEM_W1 + (unsigned)(lrow * 256) + ((((unsigned)(4 * wg + 2 + kb)) ^ xr) << 4);
    // B2 (W2, 512B rows): four ldsm4t per kk covering n-cols [128wg,128wg+64)... (64 n-cols slice)
    unsigned b2x[4];
    #pragma unroll
    for (int n = 0; n < 4; ++n)
        b2x[n] = sb + SMEM_W2 + (unsigned)(lrow * 512) + ((((unsigned)(8 * wg + 2 * n + kb)) ^ xr) << 4);
    // A(h) lane row bases, 256B rows
    const unsigned ha_r0 = (unsigned)(lrow * 256);
    const unsigned ha_r1 = (unsigned)((lrow + 16) * 256);

    // P-build mapping: thread -> (row pj, 64-half slice ps)
    const int pj = gtid >> 2, ps = gtid & 3;
    const int pj7 = pj & 7;

    // stage xj = x[pj, 64ps..64ps+64) as 32 half2 regs
    unsigned xj[32];
    {
        const float4* xrow = (const float4*)(X + (size_t)b * 8192 + pj * 256 + ps * 64);
        #pragma unroll
        for (int q = 0; q < 16; ++q) {
            float4 v = xrow[q];
            xj[2 * q]     = f2h2u(v.x, v.y);
            xj[2 * q + 1] = f2h2u(v.z, v.w);
        }
    }

    // persistent output accumulator: warp owns out cols [64wg, 64wg+64)
    float oacc[2][8][4];
    #pragma unroll
    for (int m = 0; m < 2; ++m)
        #pragma unroll
        for (int t = 0; t < 8; ++t)
            #pragma unroll
            for (int r = 0; r < 4; ++r) oacc[m][t][r] = 0.f;

    for (int c = 0; c < NCHUNK; ++c) {
        __syncthreads();  // prev chunk W readers done

        // ---- stage W1 chunk [256 d][128 h] swizzled (unit u of row d -> u^(d&7))
        for (int q = tid; q < 4096; q += THREADS) {
            int d = q >> 4, un = q & 15;
            const float* src = W1g + (size_t)d * HDIM + c * HC + un * 8;
            float4 v0 = *(const float4*)(src);
            float4 v1 = *(const float4*)(src + 4);
            uint4 o = make_uint4(f2h2u(v0.x, v0.y), f2h2u(v0.z, v0.w),
                                 f2h2u(v1.x, v1.y), f2h2u(v1.z, v1.w));
            *(uint4*)(smem + SMEM_W1 + d * 256 + ((un ^ (d & 7)) << 4)) = o;
        }
        // ---- stage W2 chunk [128 h][256 d] swizzled
        for (int q = tid; q < 4096; q += THREADS) {
            int h = q >> 5, un = q & 31;
            const float* src = W2g + (size_t)(c * HC + h) * DDIM + un * 8;
            float4 v0 = *(const float4*)(src);
            float4 v1 = *(const float4*)(src + 4);
            uint4 o = make_uint4(f2h2u(v0.x, v0.y), f2h2u(v0.z, v0.w),
                                 f2h2u(v1.x, v1.y), f2h2u(v1.z, v1.w));
            *(uint4*)(smem + SMEM_W2 + h * 512 + ((un ^ (h & 7)) << 4)) = o;
        }
        float b1v[4][2];
        #pragma unroll
        for (int t = 0; t < 4; ++t) {
            b1v[t][0] = __ldg(b1g + c * HC + 32 * wg + 8 * t + 2 * tig);
            b1v[t][1] = __ldg(b1g + c * HC + 32 * wg + 8 * t + 2 * tig + 1);
        }
        __syncthreads();  // W chunk ready

        for (int ii = 0; ii < 8; ++ii) {
            const int i0 = 4 * ii + 2 * g;
            const int i1 = i0 + 1;

            // ---- build P_i0, P_i1 (swizzled): unit (8ps+lu) -> ^(pj&7)
            {
                const float4* xi0p = (const float4*)(X + (size_t)b * 8192 + i0 * 256 + ps * 64);
                const float4* xi1p = (const float4*)(X + (size_t)b * 8192 + i1 * 256 + ps * 64);
                #pragma unroll
                for (int lu = 0; lu < 8; ++lu) {
                    unsigned off = (unsigned)(pj * 512) + ((((unsigned)(8 * ps + lu)) ^ pj7) << 4);
                    float4 v0 = xi0p[2 * lu], v1 = xi0p[2 * lu + 1];
                    uint4 o;
                    o.x = hmul2u(xj[4 * lu],     f2h2u(v0.x, v0.y));
                    o.y = hmul2u(xj[4 * lu + 1], f2h2u(v0.z, v0.w));
                    o.z = hmul2u(xj[4 * lu + 2], f2h2u(v1.x, v1.y));
                    o.w = hmul2u(xj[4 * lu + 3], f2h2u(v1.z, v1.w));
                    *(uint4*)(Pb0 + off) = o;
                    float4 u0 = xi1p[2 * lu], u1 = xi1p[2 * lu + 1];
                    uint4 p;
                    p.x = hmul2u(xj[4 * lu],     f2h2u(u0.x, u0.y));
                    p.y = hmul2u(xj[4 * lu + 1], f2h2u(u0.z, u0.w));
                    p.z = hmul2u(xj[4 * lu + 2], f2h2u(u1.x, u1.y));
                    p.w = hmul2u(xj[4 * lu + 3], f2h2u(u1.z, u1.w));
                    *(uint4*)(Pb1 + off) = p;
                }
            }
            asm volatile("bar.sync %0, %1;" :: "r"(1 + g), "r"(128));  // P ready

            // ---- GEMM1 (pair, shared B): h[i][32, 32wg..+32], K=256
            float hacc[2][2][4][4];
            #pragma unroll
            for (int i = 0; i < 2; ++i)
                #pragma unroll
                for (int m = 0; m < 2; ++m)
                    #pragma unroll
                    for (int t = 0; t < 4; ++t)
                        #pragma unroll
                        for (int r = 0; r < 4; ++r) hacc[i][m][t][r] = 0.f;
            #pragma unroll 4
            for (int kk = 0; kk < 16; ++kk) {
                unsigned off = ((((unsigned)(2 * kk + kb)) ^ xr) << 4);
                unsigned A00[4], A01[4], A10[4], A11[4], B[8];
                ldsm4(A00, uP0 + pa_r0 + off);
                ldsm4(A01, uP0 + pa_r1 + off);
                ldsm4(A10, uP1 + pa_r0 + off);
                ldsm4(A11, uP1 + pa_r1 + off);
                ldsm4t(B,     b1a + (unsigned)(kk * 4096));
                ldsm4t(B + 4, b1b + (unsigned)(kk * 4096));
                #pragma unroll
                for (int t = 0; t < 4; ++t) {
                    mma16816(hacc[0][0][t], A00, B[2 * t], B[2 * t + 1]);
                    mma16816(hacc[0][1][t], A01, B[2 * t], B[2 * t + 1]);
                    mma16816(hacc[1][0][t], A10, B[2 * t], B[2 * t + 1]);
                    mma16816(hacc[1][1][t], A11, B[2 * t], B[2 * t + 1]);
                }
            }

            // ---- bias+relu -> Hs (swizzled): col unit (4wg+t) -> ^(r&7)
            #pragma unroll
            for (int i = 0; i < 2; ++i) {
                unsigned char* Hb = i ? Hb1 : Hb0;
                #pragma unroll
                for (int m = 0; m < 2; ++m) {
                    #pragma unroll
                    for (int t = 0; t < 4; ++t) {
                        int r0 = 16 * m + gid;
                        unsigned un = ((unsigned)(4 * wg + t)) ^ (unsigned)(r0 & 7);
                        unsigned base = (unsigned)(r0 * 256) + (un << 4) + (unsigned)(4 * tig);
                        float f0 = fmaxf(hacc[i][m][t][0] + b1v[t][0], 0.f);
                        float f1 = fmaxf(hacc[i][m][t][1] + b1v[t][1], 0.f);
                        float f2 = fmaxf(hacc[i][m][t][2] + b1v[t][0], 0.f);
                        float f3 = fmaxf(hacc[i][m][t][3] + b1v[t][1], 0.f);
                        *(unsigned*)(Hb + base)        = f2h2u(f0, f1);
                        *(unsigned*)(Hb + base + 2048) = f2h2u(f2, f3);  // row r0+8
                    }
                }
            }
            asm volatile("bar.sync %0, %1;" :: "r"(1 + g), "r"(128));  // Hs ready

            // ---- GEMM2 (shared B): oacc += h0 @ W2 + h1 @ W2, K=128 each
            #pragma unroll 2
            for (int kk = 0; kk < 8; ++kk) {
                unsigned off = ((((unsigned)(2 * kk + kb)) ^ xr) << 4);
                unsigned A00[4], A01[4], A10[4], A11[4], Bb[8], Bc[8];
                ldsm4(A00, uH0 + ha_r0 + off);
                ldsm4(A01, uH0 + ha_r1 + off);
                ldsm4(A10, uH1 + ha_r0 + off);
                ldsm4(A11, uH1 + ha_r1 + off);
                ldsm4t(Bb,     b2x[0] + (unsigned)(kk * 8192));
                ldsm4t(Bb + 4, b2x[1] + (unsigned)(kk * 8192));
                ldsm4t(Bc,     b2x[2] + (unsigned)(kk * 8192));
                ldsm4t(Bc + 4, b2x[3] + (unsigned)(kk * 8192));
                #pragma unroll
                for (int t = 0; t < 4; ++t) {
                    mma16816(oacc[0][t], A00, Bb[2 * t], Bb[2 * t + 1]);
                    mma16816(oacc[1][t], A01, Bb[2 * t], Bb[2 * t + 1]);
                    mma16816(oacc[0][t + 4], A00, Bc[2 * t], Bc[2 * t + 1]);
                    mma16816(oacc[1][t + 4], A01, Bc[2 * t], Bc[2 * t + 1]);
                }
                #pragma unroll
                for (int t = 0; t < 4; ++t) {
                    mma16816(oacc[0][t], A10, Bb[2 * t], Bb[2 * t + 1]);
                    mma16816(oacc[1][t], A11, Bb[2 * t], Bb[2 * t + 1]);
                    mma16816(oacc[0][t + 4], A10, Bc[2 * t], Bc[2 * t + 1]);
                    mma16816(oacc[1][t + 4], A11, Bc[2 * t], Bc[2 * t + 1]);
                }
            }
        }
    }

    // ---- epilogue: cross-group reduce via smem (Ps region dead), add 32*b2
    __syncthreads();
    float* Os = (float*)(smem + SMEM_PS);
    if (g == 1) {
        #pragma unroll
        for (int t = 0; t < 8; ++t) {
            int col = 64 * wg + 8 * t + 2 * tig;
            #pragma unroll
            for (int m = 0; m < 2; ++m) {
                int r0 = 16 * m + gid;
                *(float2*)(Os + r0 * DDIM + col)       = make_float2(oacc[m][t][0], oacc[m][t][1]);
                *(float2*)(Os + (r0 + 8) * DDIM + col) = make_float2(oacc[m][t][2], oacc[m][t][3]);
            }
        }
    }
    __syncthreads();
    if (g == 0) {
        float* og = out + (size_t)b * NDIM * DDIM;
        #pragma unroll
        for (int t = 0; t < 8; ++t) {
            int col = 64 * wg + 8 * t + 2 * tig;
            float bb0 = 32.0f * __ldg(b2g + col);
            float bb1 = 32.0f * __ldg(b2g + col + 1);
            #pragma unroll
            for (int m = 0; m < 2; ++m) {
                int r0 = 16 * m + gid;
                float2 s0 = *(float2*)(Os + r0 * DDIM + col);
                float2 s1 = *(float2*)(Os + (r0 + 8) * DDIM + col);
                *(float2*)(og + (size_t)r0 * DDIM + col) =
                    make_float2(oacc[m][t][0] + s0.x + bb0, oacc[m][t][1] + s0.y + bb1);
                *(float2*)(og + (size_t)(r0 + 8) * DDIM + col) =
                    make_float2(oacc[m][t][2] + s1.x + bb0, oacc[m][t][3] + s1.y + bb1);
            }
        }
    }
}

extern "C" void kernel_launch(void* const* d_in, const int* in_sizes, int n_in,
                              void* d_out, int out_size) {
    (void)in_sizes; (void)n_in; (void)out_size;
    const float* X  = (const float*)d_in[0];   // [128,32,256]
    const float* W1 = (const float*)d_in[1];   // [256,1024]
    const float* b1 = (const float*)d_in[2];   // [1024]
    const float* W2 = (const float*)d_in[3];   // [1024,256]
    const float* b2 = (const float*)d_in[4];   // [256]
    float* out = (float*)d_out;                // [128,32,256]

    cudaFuncSetAttribute(fused_pair_mlp_v4,
                         cudaFuncAttributeMaxDynamicSharedMemorySize, SMEM_TOTAL);
    fused_pair_mlp_v4<<<128, THREADS, SMEM_TOTAL>>>(X, W1, b1, W2, b2, out);
}

// round 8
// speedup vs baseline: 1.0550x; 1.0012x over previous
#include <cuda_runtime.h>
#include <cuda_fp16.h>
#include <cstdint>

#define NDIM   32
#define DDIM   256
#define HDIM   1024
#define HC     128
#define NCHUNK 8
#define THREADS 256

// smem layout (bytes) — all tiles XOR-swizzled, no padding
#define SMEM_PS 0           // 4 bufs x 16384  : P [32 j][512B]
#define PS_BUF  16384
#define SMEM_W1 65536       // [256 d][256B]   : W1 chunk (k-major)
#define SMEM_W2 131072      // [128 h][512B]   : W2 chunk (k-major)
#define SMEM_HS 196608      // 4 bufs x 8192   : h [32 j][256B]
#define HS_BUF  8192
#define SMEM_TOTAL 229376   // 224KB

__device__ __forceinline__ unsigned smem_u32(const void* p) {
    unsigned a;
    asm("{ .reg .u64 t; cvta.to.shared.u64 t, %1; cvt.u32.u64 %0, t; }" : "=r"(a) : "l"(p));
    return a;
}
__device__ __forceinline__ void ldsm4(unsigned r[4], unsigned a) {
    asm volatile("ldmatrix.sync.aligned.m8n8.x4.shared.b16 {%0,%1,%2,%3}, [%4];\n"
                 : "=r"(r[0]), "=r"(r[1]), "=r"(r[2]), "=r"(r[3]) : "r"(a));
}
__device__ __forceinline__ void ldsm4t(unsigned r[4], unsigned a) {
    asm volatile("ldmatrix.sync.aligned.m8n8.x4.trans.shared.b16 {%0,%1,%2,%3}, [%4];\n"
                 : "=r"(r[0]), "=r"(r[1]), "=r"(r[2]), "=r"(r[3]) : "r"(a));
}
__device__ __forceinline__ void mma16816(float d[4], const unsigned a[4],
                                         unsigned b0, unsigned b1) {
    asm volatile("mma.sync.aligned.m16n8k16.row.col.f32.f16.f16.f32 "
                 "{%0,%1,%2,%3}, {%4,%5,%6,%7}, {%8,%9}, {%0,%1,%2,%3};\n"
                 : "+f"(d[0]), "+f"(d[1]), "+f"(d[2]), "+f"(d[3])
                 : "r"(a[0]), "r"(a[1]), "r"(a[2]), "r"(a[3]), "r"(b0), "r"(b1));
}
__device__ __forceinline__ unsigned hmul2u(unsigned a, unsigned b) {
    __half2 r = __hmul2(*(__half2*)&a, *(__half2*)&b);
    return *(unsigned*)&r;
}
__device__ __forceinline__ unsigned f2h2u(float x, float y) {
    __half2 h = __floats2half2_rn(x, y);
    return *(unsigned*)&h;
}

__global__ __launch_bounds__(THREADS, 1)
void fused_pair_mlp_v4(const float* __restrict__ X,  const float* __restrict__ W1g,
                       const float* __restrict__ b1g, const float* __restrict__ W2g,
                       const float* __restrict__ b2g, float* __restrict__ out)
{
    extern __shared__ unsigned char smem[];
    const int b = blockIdx.x, tid = threadIdx.x;
    const int w = tid >> 5, lane = tid & 31;
    const int g = w >> 2, wg = w & 3;
    const int gtid = tid & 127;
    const int gid = lane >> 2, tig = lane & 3;

    // ldmatrix lane mapping (R5-identical)
    const int mat  = lane >> 3, mr = lane & 7;
    const int lrow = (mat & 1) * 8 + mr;   // row within 16
    const int kb   = mat >> 1;             // 16B-unit offset (kh/8)
    const int xr   = lrow & 7;             // swizzle XOR key

    const unsigned sb = smem_u32(smem);
    const unsigned uP0 = sb + SMEM_PS + (unsigned)(g * 2) * PS_BUF;
    const unsigned uP1 = uP0 + PS_BUF;
    const unsigned uH0 = sb + SMEM_HS + (unsigned)(g * 2) * HS_BUF;
    const unsigned uH1 = uH0 + HS_BUF;
    unsigned char* Pb0 = smem + SMEM_PS + (g * 2) * PS_BUF;
    unsigned char* Pb1 = Pb0 + PS_BUF;
    unsigned char* Hb0 = smem + SMEM_HS + (g * 2) * HS_BUF;
    unsigned char* Hb1 = Hb0 + HS_BUF;

    // A(P) lane row bases (rows 0-15 / 16-31), 512B rows
    const unsigned pa_r0 = (unsigned)(lrow * 512);
    const unsigned pa_r1 = (unsigned)((lrow + 16) * 512);
    // B1 (W1, 256B rows): two ldsm4t per kk covering n-cols [32wg,32wg+32)
    const unsigned b1a = sb + SMEM_W1 + (unsigned)(lrow * 256) + ((((unsigned)(4 * wg + kb)) ^ xr) << 4);
    const unsigned b1b = sb + SMEM_W1 + (unsigned)(lrow * 256) + ((((unsigned)(4 * wg + 2 + kb)) ^ xr) << 4);
    // B2 (W2, 512B rows): four ldsm4t per kk covering n-cols [128wg,128wg+64)... (64 n-cols slice)
    unsigned b2x[4];
    #pragma unroll
    for (int n = 0; n < 4; ++n)
        b2x[n] = sb + SMEM_W2 + (unsigned)(lrow * 512) + ((((unsigned)(8 * wg + 2 * n + kb)) ^ xr) << 4);
    // A(h) lane row bases, 256B rows
    const unsigned ha_r0 = (unsigned)(lrow * 256);
    const unsigned ha_r1 = (unsigned)((lrow + 16) * 256);

    // P-build mapping: thread -> (row pj, 64-half slice ps)
    const int pj = gtid >> 2, ps = gtid & 3;
    const int pj7 = pj & 7;

    // stage xj = x[pj, 64ps..64ps+64) as 32 half2 regs
    unsigned xj[32];
    {
        const float4* xrow = (const float4*)(X + (size_t)b * 8192 + pj * 256 + ps * 64);
        #pragma unroll
        for (int q = 0; q < 16; ++q) {
            float4 v = xrow[q];
            xj[2 * q]     = f2h2u(v.x, v.y);
            xj[2 * q + 1] = f2h2u(v.z, v.w);
        }
    }

    // persistent output accumulator: warp owns out cols [64wg, 64wg+64)
    float oacc[2][8][4];
    #pragma unroll
    for (int m = 0; m < 2; ++m)
        #pragma unroll
        for (int t = 0; t < 8; ++t)
            #pragma unroll
            for (int r = 0; r < 4; ++r) oacc[m][t][r] = 0.f;

    for (int c = 0; c < NCHUNK; ++c) {
        __syncthreads();  // prev chunk W readers done

        // ---- stage W1 chunk [256 d][128 h] swizzled (unit u of row d -> u^(d&7))
        for (int q = tid; q < 4096; q += THREADS) {
            int d = q >> 4, un = q & 15;
            const float* src = W1g + (size_t)d * HDIM + c * HC + un * 8;
            float4 v0 = *(const float4*)(src);
            float4 v1 = *(const float4*)(src + 4);
            uint4 o = make_uint4(f2h2u(v0.x, v0.y), f2h2u(v0.z, v0.w),
                                 f2h2u(v1.x, v1.y), f2h2u(v1.z, v1.w));
            *(uint4*)(smem + SMEM_W1 + d * 256 + ((un ^ (d & 7)) << 4)) = o;
        }
        // ---- stage W2 chunk [128 h][256 d] swizzled
        for (int q = tid; q < 4096; q += THREADS) {
            int h = q >> 5, un = q & 31;
            const float* src = W2g + (size_t)(c * HC + h) * DDIM + un * 8;
            float4 v0 = *(const float4*)(src);
            float4 v1 = *(const float4*)(src + 4);
            uint4 o = make_uint4(f2h2u(v0.x, v0.y), f2h2u(v0.z, v0.w),
                                 f2h2u(v1.x, v1.y), f2h2u(v1.z, v1.w));
            *(uint4*)(smem + SMEM_W2 + h * 512 + ((un ^ (h & 7)) << 4)) = o;
        }
        float b1v[4][2];
        #pragma unroll
        for (int t = 0; t < 4; ++t) {
            b1v[t][0] = __ldg(b1g + c * HC + 32 * wg + 8 * t + 2 * tig);
            b1v[t][1] = __ldg(b1g + c * HC + 32 * wg + 8 * t + 2 * tig + 1);
        }
        __syncthreads();  // W chunk ready

        for (int ii = 0; ii < 8; ++ii) {
            const int i0 = 4 * ii + 2 * g;
            const int i1 = i0 + 1;

            // ---- build P_i0, P_i1 (swizzled): unit (8ps+lu) -> ^(pj&7)
            {
                const float4* xi0p = (const float4*)(X + (size_t)b * 8192 + i0 * 256 + ps * 64);
                const float4* xi1p = (const float4*)(X + (size_t)b * 8192 + i1 * 256 + ps * 64);
                #pragma unroll
                for (int lu = 0; lu < 8; ++lu) {
                    unsigned off = (unsigned)(pj * 512) + ((((unsigned)(8 * ps + lu)) ^ pj7) << 4);
                    float4 v0 = xi0p[2 * lu], v1 = xi0p[2 * lu + 1];
                    uint4 o;
                    o.x = hmul2u(xj[4 * lu],     f2h2u(v0.x, v0.y));
                    o.y = hmul2u(xj[4 * lu + 1], f2h2u(v0.z, v0.w));
                    o.z = hmul2u(xj[4 * lu + 2], f2h2u(v1.x, v1.y));
                    o.w = hmul2u(xj[4 * lu + 3], f2h2u(v1.z, v1.w));
                    *(uint4*)(Pb0 + off) = o;
                    float4 u0 = xi1p[2 * lu], u1 = xi1p[2 * lu + 1];
                    uint4 p;
                    p.x = hmul2u(xj[4 * lu],     f2h2u(u0.x, u0.y));
                    p.y = hmul2u(xj[4 * lu + 1], f2h2u(u0.z, u0.w));
                    p.z = hmul2u(xj[4 * lu + 2], f2h2u(u1.x, u1.y));
                    p.w = hmul2u(xj[4 * lu + 3], f2h2u(u1.z, u1.w));
                    *(uint4*)(Pb1 + off) = p;
                }
            }
            asm volatile("bar.sync %0, %1;" :: "r"(1 + g), "r"(128));  // P ready

            // ---- GEMM1 (pair, shared B): h[i][32, 32wg..+32], K=256
            float hacc[2][2][4][4];
            #pragma unroll
            for (int i = 0; i < 2; ++i)
                #pragma unroll
                for (int m = 0; m < 2; ++m)
                    #pragma unroll
                    for (int t = 0; t < 4; ++t)
                        #pragma unroll
                        for (int r = 0; r < 4; ++r) hacc[i][m][t][r] = 0.f;
            #pragma unroll 4
            for (int kk = 0; kk < 16; ++kk) {
                unsigned off = ((((unsigned)(2 * kk + kb)) ^ xr) << 4);
                unsigned A00[4], A01[4], A10[4], A11[4], B[8];
                ldsm4(A00, uP0 + pa_r0 + off);
                ldsm4(A01, uP0 + pa_r1 + off);
                ldsm4(A10, uP1 + pa_r0 + off);
                ldsm4(A11, uP1 + pa_r1 + off);
                ldsm4t(B,     b1a + (unsigned)(kk * 4096));
                ldsm4t(B + 4, b1b + (unsigned)(kk * 4096));
                #pragma unroll
                for (int t = 0; t < 4; ++t) {
                    mma16816(hacc[0][0][t], A00, B[2 * t], B[2 * t + 1]);
                    mma16816(hacc[0][1][t], A01, B[2 * t], B[2 * t + 1]);
                    mma16816(hacc[1][0][t], A10, B[2 * t], B[2 * t + 1]);
                    mma16816(hacc[1][1][t], A11, B[2 * t], B[2 * t + 1]);
                }
            }

            // ---- bias+relu -> Hs (swizzled): col unit (4wg+t) -> ^(r&7)
            #pragma unroll
            for (int i = 0; i < 2; ++i) {
                unsigned char* Hb = i ? Hb1 : Hb0;
                #pragma unroll
                for (int m = 0; m < 2; ++m) {
                    #pragma unroll
                    for (int t = 0; t < 4; ++t) {
                        int r0 = 16 * m + gid;
                        unsigned un = ((unsigned)(4 * wg + t)) ^ (unsigned)(r0 & 7);
                        unsigned base = (unsigned)(r0 * 256) + (un << 4) + (unsigned)(4 * tig);
                        float f0 = fmaxf(hacc[i][m][t][0] + b1v[t][0], 0.f);
                        float f1 = fmaxf(hacc[i][m][t][1] + b1v[t][1], 0.f);
                        float f2 = fmaxf(hacc[i][m][t][2] + b1v[t][0], 0.f);
                        float f3 = fmaxf(hacc[i][m][t][3] + b1v[t][1], 0.f);
                        *(unsigned*)(Hb + base)        = f2h2u(f0, f1);
                        *(unsigned*)(Hb + base + 2048) = f2h2u(f2, f3);  // row r0+8
                    }
                }
            }
            asm volatile("bar.sync %0, %1;" :: "r"(1 + g), "r"(128));  // Hs ready

            // ---- GEMM2 (shared B): oacc += h0 @ W2 + h1 @ W2, K=128 each
            #pragma unroll 2
            for (int kk = 0; kk < 8; ++kk) {
                unsigned off = ((((unsigned)(2 * kk + kb)) ^ xr) << 4);
                unsigned A00[4], A01[4], A10[4], A11[4], Bb[8], Bc[8];
                ldsm4(A00, uH0 + ha_r0 + off);
                ldsm4(A01, uH0 + ha_r1 + off);
                ldsm4(A10, uH1 + ha_r0 + off);
                ldsm4(A11, uH1 + ha_r1 + off);
                ldsm4t(Bb,     b2x[0] + (unsigned)(kk * 8192));
                ldsm4t(Bb + 4, b2x[1] + (unsigned)(kk * 8192));
                ldsm4t(Bc,     b2x[2] + (unsigned)(kk * 8192));
                ldsm4t(Bc + 4, b2x[3] + (unsigned)(kk * 8192));
                #pragma unroll
                for (int t = 0; t < 4; ++t) {
                    mma16816(oacc[0][t], A00, Bb[2 * t], Bb[2 * t + 1]);
                    mma16816(oacc[1][t], A01, Bb[2 * t], Bb[2 * t + 1]);
                    mma16816(oacc[0][t + 4], A00, Bc[2 * t], Bc[2 * t + 1]);
                    mma16816(oacc[1][t + 4], A01, Bc[2 * t], Bc[2 * t + 1]);
                }
                #pragma unroll
                for (int t = 0; t < 4; ++t) {
                    mma16816(oacc[0][t], A10, Bb[2 * t], Bb[2 * t + 1]);
                    mma16816(oacc[1][t], A11, Bb[2 * t], Bb[2 * t + 1]);
                    mma16816(oacc[0][t + 4], A10, Bc[2 * t], Bc[2 * t + 1]);
                    mma16816(oacc[1][t + 4], A11, Bc[2 * t], Bc[2 * t + 1]);
                }
            }
        }
    }

    // ---- epilogue: cross-group reduce via smem (Ps region dead), add 32*b2
    __syncthreads();
    float* Os = (float*)(smem + SMEM_PS);
    if (g == 1) {
        #pragma unroll
        for (int t = 0; t < 8; ++t) {
            int col = 64 * wg + 8 * t + 2 * tig;
            #pragma unroll
            for (int m = 0; m < 2; ++m) {
                int r0 = 16 * m + gid;
                *(float2*)(Os + r0 * DDIM + col)       = make_float2(oacc[m][t][0], oacc[m][t][1]);
                *(float2*)(Os + (r0 + 8) * DDIM + col) = make_float2(oacc[m][t][2], oacc[m][t][3]);
            }
        }
    }
    __syncthreads();
    if (g == 0) {
        float* og = out + (size_t)b * NDIM * DDIM;
        #pragma unroll
        for (int t = 0; t < 8; ++t) {
            int col = 64 * wg + 8 * t + 2 * tig;
            float bb0 = 32.0f * __ldg(b2g + col);
            float bb1 = 32.0f * __ldg(b2g + col + 1);
            #pragma unroll
            for (int m = 0; m < 2; ++m) {
                int r0 = 16 * m + gid;
                float2 s0 = *(float2*)(Os + r0 * DDIM + col);
                float2 s1 = *(float2*)(Os + (r0 + 8) * DDIM + col);
                *(float2*)(og + (size_t)r0 * DDIM + col) =
                    make_float2(oacc[m][t][0] + s0.x + bb0, oacc[m][t][1] + s0.y + bb1);
                *(float2*)(og + (size_t)(r0 + 8) * DDIM + col) =
                    make_float2(oacc[m][t][2] + s1.x + bb0, oacc[m][t][3] + s1.y + bb1);
            }
        }
    }
}

extern "C" void kernel_launch(void* const* d_in, const int* in_sizes, int n_in,
                              void* d_out, int out_size) {
    (void)in_sizes; (void)n_in; (void)out_size;
    const float* X  = (const float*)d_in[0];   // [128,32,256]
    const float* W1 = (const float*)d_in[1];   // [256,1024]
    const float* b1 = (const float*)d_in[2];   // [1024]
    const float* W2 = (const float*)d_in[3];   // [1024,256]
    const float* b2 = (const float*)d_in[4];   // [256]
    float* out = (float*)d_out;                // [128,32,256]

    cudaFuncSetAttribute(fused_pair_mlp_v4,
                         cudaFuncAttributeMaxDynamicSharedMemorySize, SMEM_TOTAL);
    fused_pair_mlp_v4<<<128, THREADS, SMEM_TOTAL>>>(X, W1, b1, W2, b2, out);
}